// round 14
// baseline (speedup 1.0000x reference)
#include <cuda_runtime.h>
#include <cuda_fp16.h>
#include <cstdint>

#define Hdim 256
#define Bdim 2048
#define Tdim 512
#define Vdim 64
#define NB   16          // batches per CTA -> 128 CTAs
#define NTH  512         // 16 warps: pair p = (w&7), K-half = (w>>3)
#define HSTR 264         // h row stride in halfs (528B)
#define PSTR 266         // P row stride in floats
#define ESTR 68          // embT row stride in floats

// ---- shared memory layout (bytes) ----
#define SM_P    0                      // P[64][PSTR] f32 = 68096
#define SM_H0   68096                  // h buf0: 16 x 264 halfs = 8448
#define SM_H1   76544                  // h buf1: 8448
#define SM_TOK  84992                  // tokens [512][16] int = 32768
#define SM_MBAR 117760                 // mbarrier (16B pad)
#define SM_SCR  117776                 // partial exchange: 16 slots x 512B = 8192
#define SM_EMBT 125968                 // transient embT f32 [256][ESTR] = 69632
#define SMEM_TOTAL (125968 + 69632)    // 195600

// ---------------------------------------------------------------------------
__device__ __forceinline__ uint32_t smem_u32(const void* p) {
    uint32_t a;
    asm("{ .reg .u64 t; cvta.to.shared.u64 t, %1; cvt.u32.u64 %0, t; }"
        : "=r"(a) : "l"(p));
    return a;
}
// sigmoid via single-MUFU tanh: s = 0.5*tanh(0.5x) + 0.5
__device__ __forceinline__ float sigmoid_t(float x) {
    float t;
    asm("tanh.approx.f32 %0, %1;" : "=f"(t) : "f"(0.5f * x));
    return fmaf(0.5f, t, 0.5f);
}
__device__ __forceinline__ void ffma2(unsigned long long& d,
                                      unsigned long long a, unsigned long long b) {
    asm("fma.rn.f32x2 %0, %1, %2, %0;" : "+l"(d) : "l"(a), "l"(b));
}
__device__ __forceinline__ unsigned long long pack2(float lo, float hi) {
    unsigned long long r;
    asm("mov.b64 %0, {%1, %2};" : "=l"(r) : "f"(lo), "f"(hi));
    return r;
}
__device__ __forceinline__ void mma16816(float* d, const uint32_t* a,
                                         uint32_t b0, uint32_t b1) {
    asm volatile(
        "mma.sync.aligned.m16n8k16.row.col.f32.f16.f16.f32 "
        "{%0,%1,%2,%3}, {%4,%5,%6,%7}, {%8,%9}, {%0,%1,%2,%3};"
        : "+f"(d[0]), "+f"(d[1]), "+f"(d[2]), "+f"(d[3])
        : "r"(a[0]), "r"(a[1]), "r"(a[2]), "r"(a[3]), "r"(b0), "r"(b1));
}
__device__ __forceinline__ void ldmx4(uint32_t& r0, uint32_t& r1,
                                      uint32_t& r2, uint32_t& r3, uint32_t addr) {
    asm volatile(
        "ldmatrix.sync.aligned.m8n8.x4.shared.b16 {%0,%1,%2,%3}, [%4];"
        : "=r"(r0), "=r"(r1), "=r"(r2), "=r"(r3) : "r"(addr));
}
#define MBAR_INIT(mb, c) asm volatile("mbarrier.init.shared.b64 [%0], %1;" \
                                      :: "r"(mb), "r"(c) : "memory")
#define MBAR_ARRIVE(mb)  asm volatile("mbarrier.arrive.shared.b64 _, [%0];" \
                                      :: "r"(mb) : "memory")
__device__ __forceinline__ void mbar_wait(uint32_t mb, uint32_t parity) {
    asm volatile(
        "{ .reg .pred P;\n\t"
        "W_%=:\n\t"
        "mbarrier.try_wait.parity.acquire.cta.shared::cta.b64 P, [%0], %1, 0x989680;\n\t"
        "@P bra.uni D_%=;\n\t"
        "bra.uni W_%=;\n\t"
        "D_%=: }"
        :: "r"(mb), "r"(parity) : "memory");
}
__device__ __forceinline__ void bar_pair(int id) {
    asm volatile("bar.sync %0, 64;" :: "r"(id) : "memory");
}

// ---------------------------------------------------------------------------
// Persistent RNN, balanced K-split warp pairs.
// Pair p = warps (p, p+8) [same SMSP] owns outputs [32p, 32p+32) (4 n8
// tiles, breg register-resident). Warp (p,k) MMAs K-half k (8 chunks -> 8
// ldmx4 instead of 16), producing partials for all 4 tiles. It SENDS tiles
// {2(1-k), 2(1-k)+1} as 4x half2 in one STS.128 (lane-aligned), syncs
// bar.sync(p+1, 64), reads the partner's STS.128, and REDUCES its own
// tiles {2k, 2k+1}: add, sigmoid, h' STS, output STG. Both warps do equal
// epilogue work. Main recurrence phased by the proven single mbarrier
// (every thread arrives once per step; pair barriers are leaf syncs both
// partners always reach -> no cycles, no parity skew).
// ---------------------------------------------------------------------------
__global__ __launch_bounds__(NTH, 1)
void k_rnn(const int* __restrict__ tokens,
           const float* __restrict__ h0,
           const float* __restrict__ emb,
           const float* __restrict__ W,
           const float* __restrict__ bias,
           float* __restrict__ out) {
    extern __shared__ char smem[];
    const uint32_t sbase = smem_u32(smem);
    float* Psm  = (float*)(smem + SM_P);
    int*   toks = (int*)(smem + SM_TOK);
    const uint32_t mbar = sbase + SM_MBAR;

    const int tid  = threadIdx.x;
    const int wid  = tid >> 5;
    const int lane = tid & 31;
    const int g    = lane >> 2;     // 0..7
    const int r    = lane & 3;      // 0..3
    const int pair = wid & 7;       // 0..7
    const int kh   = wid >> 3;      // K-half: 0 or 1
    const int bbase = blockIdx.x * NB;

    // ============== Prologue ==============
    {
        float* embT = (float*)(smem + SM_EMBT);
        for (int idx = tid; idx < Vdim * Hdim; idx += NTH) {
            int v = idx >> 8, k = idx & 255;
            embT[(size_t)k * ESTR + v] = emb[(size_t)v * Hdim + k];
        }
    }
    __syncthreads();
    {   // P[v][o] = bias[o] + emb[v,:]·Wx[o,:]; thread: o = tid&255, 2 v-groups
        const float* embT = (const float*)(smem + SM_EMBT);
        const int o = tid & 255;
        const int vg0 = (tid >> 8) * 2;
        const float bo = bias[o];
        const float4* wrow = (const float4*)(W + (size_t)o * (2 * Hdim));
        for (int vg = vg0; vg < vg0 + 2; ++vg) {
            unsigned long long acc[8];
#pragma unroll
            for (int i = 0; i < 8; ++i) acc[i] = pack2(0.f, 0.f);
            for (int k4 = 0; k4 < Hdim / 4; ++k4) {
                float4 wv = wrow[k4];
#pragma unroll
                for (int kk = 0; kk < 4; ++kk) {
                    int k = k4 * 4 + kk;
                    float w = (kk == 0) ? wv.x : (kk == 1) ? wv.y : (kk == 2) ? wv.z : wv.w;
                    unsigned long long wpair = pack2(w, w);
                    const ulonglong2* ep =
                        (const ulonglong2*)(embT + (size_t)k * ESTR + vg * 16);
                    ulonglong2 e0 = ep[0], e1 = ep[1], e2 = ep[2], e3 = ep[3];
                    ffma2(acc[0], wpair, e0.x); ffma2(acc[1], wpair, e0.y);
                    ffma2(acc[2], wpair, e1.x); ffma2(acc[3], wpair, e1.y);
                    ffma2(acc[4], wpair, e2.x); ffma2(acc[5], wpair, e2.y);
                    ffma2(acc[6], wpair, e3.x); ffma2(acc[7], wpair, e3.y);
                }
            }
#pragma unroll
            for (int i = 0; i < 8; ++i) {
                float lo = __uint_as_float((uint32_t)(acc[i] & 0xffffffffu));
                float hi = __uint_as_float((uint32_t)(acc[i] >> 32));
                int v0 = vg * 16 + 2 * i;
                Psm[(size_t)v0 * PSTR + o]       = bo + lo;
                Psm[(size_t)(v0 + 1) * PSTR + o] = bo + hi;
            }
        }
    }
    // B fragments: 4 n8 tiles over this warp's K-half (8 chunks)
    uint32_t breg[4][8][2];
#pragma unroll
    for (int nt = 0; nt < 4; ++nt) {
        int n = pair * 32 + nt * 8 + g;
        const float* wr = W + (size_t)n * (2 * Hdim) + Hdim;
#pragma unroll
        for (int c = 0; c < 8; ++c) {
            int k0 = (kh * 8 + c) * 16 + 2 * r;
            float2 lo = *(const float2*)&wr[k0];
            float2 hi = *(const float2*)&wr[k0 + 8];
            __half2 hlo = __floats2half2_rn(lo.x, lo.y);
            __half2 hhi = __floats2half2_rn(hi.x, hi.y);
            breg[nt][c][0] = *(uint32_t*)&hlo;
            breg[nt][c][1] = *(uint32_t*)&hhi;
        }
    }
    for (int idx = tid; idx < NB * Tdim; idx += NTH) {
        int b = idx >> 9, t = idx & 511;
        toks[t * NB + b] = tokens[(size_t)(bbase + b) * Tdim + t];
    }
    {
        __half* hb = (__half*)(smem + SM_H0);
        for (int idx = tid; idx < NB * Hdim; idx += NTH) {
            int b = idx >> 8, k = idx & 255;
            hb[(size_t)b * HSTR + k] =
                __float2half_rn(h0[(size_t)(bbase + b) * Hdim + k]);
        }
    }
    if (tid == 0) MBAR_INIT(mbar, NTH);
    __syncthreads();
    MBAR_ARRIVE(mbar);       // phase 0: h(0) published

    // ldmatrix lane address (chunk c within own K-half: +c*32)
    const uint32_t ldm_base =
        (uint32_t)((lane & 15) * (HSTR * 2) + (lane >> 4) * 16)
        + (uint32_t)(kh * 8 * 32);
    // reduce tiles rt = 2kh + {0,1}; their base cols for this thread
    const int oR0 = pair * 32 + (2 * kh) * 8 + 2 * r;      // tile 2kh
    const int oR1 = oR0 + 8;                               // tile 2kh+1
    // exchange slots (512B each): own = (pair, kh), partner = (pair, 1-kh)
    const uint32_t scr_own  = sbase + SM_SCR + (uint32_t)((pair * 2 + kh) * 512 + lane * 16);
    const uint32_t scr_part = sbase + SM_SCR + (uint32_t)((pair * 2 + (1 - kh)) * 512 + lane * 16);
    const int st0 = 2 * (1 - kh);                          // first send tile
    float* const outcta = out + (size_t)bbase * Hdim;

    // ============== Recurrent loop ==============
    for (int t = 0; t < Tdim; ++t) {
        // token + P prefetch for the REDUCE tiles (stable regions, pre-wait)
        const int tk0 = toks[t * NB + g];
        const int tk1 = toks[t * NB + g + 8];
        float2 pA0 = *(const float2*)&Psm[(size_t)tk0 * PSTR + oR0];
        float2 pA1 = *(const float2*)&Psm[(size_t)tk1 * PSTR + oR0];
        float2 pB0 = *(const float2*)&Psm[(size_t)tk0 * PSTR + oR1];
        float2 pB1 = *(const float2*)&Psm[(size_t)tk1 * PSTR + oR1];

        float d[4][4];
#pragma unroll
        for (int nt = 0; nt < 4; ++nt)
#pragma unroll
            for (int j = 0; j < 4; ++j) d[nt][j] = 0.f;
        d[2 * kh][0] = pA0.x;     d[2 * kh][1] = pA0.y;
        d[2 * kh][2] = pA1.x;     d[2 * kh][3] = pA1.y;
        d[2 * kh + 1][0] = pB0.x; d[2 * kh + 1][1] = pB0.y;
        d[2 * kh + 1][2] = pB1.x; d[2 * kh + 1][3] = pB1.y;

        mbar_wait(mbar, (uint32_t)(t & 1));
        const uint32_t abuf = sbase + ((t & 1) ? SM_H1 : SM_H0) + ldm_base;

        // own K-half: 8 chunks x 4 tiles (A shared; 4 independent chains)
#pragma unroll
        for (int c = 0; c < 8; ++c) {
            uint32_t a[4];
            ldmx4(a[0], a[1], a[2], a[3], abuf + (uint32_t)c * 32);
            mma16816(d[0], a, breg[0][c][0], breg[0][c][1]);
            mma16816(d[1], a, breg[1][c][0], breg[1][c][1]);
            mma16816(d[2], a, breg[2][c][0], breg[2][c][1]);
            mma16816(d[3], a, breg[3][c][0], breg[3][c][1]);
        }

        // send partner's tiles as 4x half2 in one STS.128
        {
            __half2 q0 = __floats2half2_rn(d[st0][0],     d[st0][1]);
            __half2 q1 = __floats2half2_rn(d[st0][2],     d[st0][3]);
            __half2 q2 = __floats2half2_rn(d[st0 + 1][0], d[st0 + 1][1]);
            __half2 q3 = __floats2half2_rn(d[st0 + 1][2], d[st0 + 1][3]);
            uint4 v = make_uint4(*(uint32_t*)&q0, *(uint32_t*)&q1,
                                 *(uint32_t*)&q2, *(uint32_t*)&q3);
            asm volatile("st.shared.v4.b32 [%0], {%1,%2,%3,%4};"
                         :: "r"(scr_own), "r"(v.x), "r"(v.y), "r"(v.z), "r"(v.w)
                         : "memory");
        }
        bar_pair(pair + 1);
        uint4 v;
        asm volatile("ld.shared.v4.b32 {%0,%1,%2,%3}, [%4];"
                     : "=r"(v.x), "=r"(v.y), "=r"(v.z), "=r"(v.w)
                     : "r"(scr_part));
        float2 f0 = __half22float2(*(__half2*)&v.x);
        float2 f1 = __half22float2(*(__half2*)&v.y);
        float2 f2 = __half22float2(*(__half2*)&v.z);
        float2 f3 = __half22float2(*(__half2*)&v.w);

        // reduce own tiles, sigmoid, STS h(t+1), arrive
        float s[2][4];
        s[0][0] = sigmoid_t(d[2 * kh][0] + f0.x);
        s[0][1] = sigmoid_t(d[2 * kh][1] + f0.y);
        s[0][2] = sigmoid_t(d[2 * kh][2] + f1.x);
        s[0][3] = sigmoid_t(d[2 * kh][3] + f1.y);
        s[1][0] = sigmoid_t(d[2 * kh + 1][0] + f2.x);
        s[1][1] = sigmoid_t(d[2 * kh + 1][1] + f2.y);
        s[1][2] = sigmoid_t(d[2 * kh + 1][2] + f3.x);
        s[1][3] = sigmoid_t(d[2 * kh + 1][3] + f3.y);

        __half* hn = (__half*)(smem + ((t & 1) ? SM_H0 : SM_H1));
        *(__half2*)&hn[(size_t)g * HSTR + oR0]       = __floats2half2_rn(s[0][0], s[0][1]);
        *(__half2*)&hn[(size_t)(g + 8) * HSTR + oR0] = __floats2half2_rn(s[0][2], s[0][3]);
        *(__half2*)&hn[(size_t)g * HSTR + oR1]       = __floats2half2_rn(s[1][0], s[1][1]);
        *(__half2*)&hn[(size_t)(g + 8) * HSTR + oR1] = __floats2half2_rn(s[1][2], s[1][3]);
        MBAR_ARRIVE(mbar);

        // output drain in the post-arrive shadow
        float* outp = outcta + (size_t)t * (Bdim * Hdim);
        *(float2*)&outp[(size_t)g * Hdim + oR0]       = make_float2(s[0][0], s[0][1]);
        *(float2*)&outp[(size_t)(g + 8) * Hdim + oR0] = make_float2(s[0][2], s[0][3]);
        *(float2*)&outp[(size_t)g * Hdim + oR1]       = make_float2(s[1][0], s[1][1]);
        *(float2*)&outp[(size_t)(g + 8) * Hdim + oR1] = make_float2(s[1][2], s[1][3]);
    }
}

// ---------------------------------------------------------------------------
// Harness entry.
// Inputs: tokens(i32 2048x512), h0(f32 2048x256), emb(f32 64x256),
//         W(f32 256x512), b(f32 256).  Output: f32 (512,2048,256)
// ---------------------------------------------------------------------------
extern "C" void kernel_launch(void* const* d_in, const int* in_sizes, int n_in,
                              void* d_out, int out_size) {
    const int*   tokens = (const int*)d_in[0];
    const float* h0     = (const float*)d_in[1];
    const float* emb    = (const float*)d_in[2];
    const float* W      = (const float*)d_in[3];
    const float* bias   = (const float*)d_in[4];
    float*       out    = (float*)d_out;
    (void)in_sizes; (void)n_in; (void)out_size;

    cudaFuncSetAttribute(k_rnn, cudaFuncAttributeMaxDynamicSharedMemorySize, SMEM_TOTAL);
    k_rnn<<<Bdim / NB, NTH, SMEM_TOTAL>>>(tokens, h0, emb, W, bias, out);
}

// round 15
// speedup vs baseline: 1.0932x; 1.0932x over previous
#include <cuda_runtime.h>
#include <cuda_fp16.h>
#include <cstdint>

#define Hdim 256
#define Bdim 2048
#define Tdim 512
#define Vdim 64
#define NB   16          // batches per CTA -> 128 CTAs
#define NTH  512         // 16 warps, each owns 16 outputs (2 n8 tiles)
#define PSTR 266         // P row stride in floats
#define ESTR 68          // embT row stride in floats

// ---- shared memory layout (bytes) ----
// h exchanged in MMA A-FRAGMENT layout: slot[c][lane] = uint4 (16B), c = chunk
// = producer warp id. Buffer = 16 slots x 32 lanes x 16B = 8192 B.
#define SM_P    0                      // P[64][PSTR] f32 = 68096
#define SM_F0   68096                  // h frag buf0: 8192
#define SM_F1   76288                  // h frag buf1: 8192
#define SM_TOK  84480                  // tokens [512][16] int = 32768
#define SM_MBAR 117248                 // mbarrier (pad 128)
#define SM_EMBT 117376                 // transient embT f32 [256][ESTR] = 69632
#define SMEM_TOTAL (117376 + 69632)    // 187008

// ---------------------------------------------------------------------------
__device__ __forceinline__ uint32_t smem_u32(const void* p) {
    uint32_t a;
    asm("{ .reg .u64 t; cvta.to.shared.u64 t, %1; cvt.u32.u64 %0, t; }"
        : "=r"(a) : "l"(p));
    return a;
}
// sigmoid via single-MUFU tanh: s = 0.5*tanh(0.5x) + 0.5
__device__ __forceinline__ float sigmoid_t(float x) {
    float t;
    asm("tanh.approx.f32 %0, %1;" : "=f"(t) : "f"(0.5f * x));
    return fmaf(0.5f, t, 0.5f);
}
__device__ __forceinline__ void ffma2(unsigned long long& d,
                                      unsigned long long a, unsigned long long b) {
    asm("fma.rn.f32x2 %0, %1, %2, %0;" : "+l"(d) : "l"(a), "l"(b));
}
__device__ __forceinline__ unsigned long long pack2(float lo, float hi) {
    unsigned long long r;
    asm("mov.b64 %0, {%1, %2};" : "=l"(r) : "f"(lo), "f"(hi));
    return r;
}
__device__ __forceinline__ void mma16816(float* d, const uint32_t* a,
                                         uint32_t b0, uint32_t b1) {
    asm volatile(
        "mma.sync.aligned.m16n8k16.row.col.f32.f16.f16.f32 "
        "{%0,%1,%2,%3}, {%4,%5,%6,%7}, {%8,%9}, {%0,%1,%2,%3};"
        : "+f"(d[0]), "+f"(d[1]), "+f"(d[2]), "+f"(d[3])
        : "r"(a[0]), "r"(a[1]), "r"(a[2]), "r"(a[3]), "r"(b0), "r"(b1));
}
__device__ __forceinline__ void lds128(uint32_t* a, uint32_t addr) {
    asm volatile("ld.shared.v4.b32 {%0,%1,%2,%3}, [%4];"
                 : "=r"(a[0]), "=r"(a[1]), "=r"(a[2]), "=r"(a[3]) : "r"(addr));
}
__device__ __forceinline__ void sts128(uint32_t addr, uint32_t v0, uint32_t v1,
                                       uint32_t v2, uint32_t v3) {
    asm volatile("st.shared.v4.b32 [%0], {%1,%2,%3,%4};"
                 :: "r"(addr), "r"(v0), "r"(v1), "r"(v2), "r"(v3) : "memory");
}
#define MBAR_INIT(mb, c) asm volatile("mbarrier.init.shared.b64 [%0], %1;" \
                                      :: "r"(mb), "r"(c) : "memory")
#define MBAR_ARRIVE(mb)  asm volatile("mbarrier.arrive.shared.b64 _, [%0];" \
                                      :: "r"(mb) : "memory")
__device__ __forceinline__ void mbar_wait(uint32_t mb, uint32_t parity) {
    asm volatile(
        "{ .reg .pred P;\n\t"
        "W_%=:\n\t"
        "mbarrier.try_wait.parity.acquire.cta.shared::cta.b64 P, [%0], %1, 0x989680;\n\t"
        "@P bra.uni D_%=;\n\t"
        "bra.uni W_%=;\n\t"
        "D_%=: }"
        :: "r"(mb), "r"(parity) : "memory");
}

// ---------------------------------------------------------------------------
// Persistent RNN: CTA owns 16 batch chains for 512 steps.
// D[16 batch, 256 out] = h[16,256] x WhT; warp w owns outputs [16w, 16w+16)
// (2 n8 tiles, breg register-resident). h is exchanged in MMA A-FRAGMENT
// layout: warp w's epilogue half2 s-values ARE, lane-for-lane, every
// consumer's A-fragment for chunk w. Producer: one STS.128; consumer: one
// LDS.128 per chunk (replaces ldmatrix + scattered STS + HSTR addressing).
// Numerically bit-identical to the 602.7us R10 kernel.
// ---------------------------------------------------------------------------
__global__ __launch_bounds__(NTH, 1)
void k_rnn(const int* __restrict__ tokens,
           const float* __restrict__ h0,
           const float* __restrict__ emb,
           const float* __restrict__ W,
           const float* __restrict__ bias,
           float* __restrict__ out) {
    extern __shared__ char smem[];
    const uint32_t sbase = smem_u32(smem);
    float* Psm  = (float*)(smem + SM_P);
    int*   toks = (int*)(smem + SM_TOK);
    const uint32_t mbar = sbase + SM_MBAR;

    const int tid  = threadIdx.x;
    const int wid  = tid >> 5;
    const int lane = tid & 31;
    const int g    = lane >> 2;     // 0..7
    const int r    = lane & 3;      // 0..3
    const int bbase = blockIdx.x * NB;

    // ============== Prologue ==============
    {
        float* embT = (float*)(smem + SM_EMBT);
        for (int idx = tid; idx < Vdim * Hdim; idx += NTH) {
            int v = idx >> 8, k = idx & 255;
            embT[(size_t)k * ESTR + v] = emb[(size_t)v * Hdim + k];
        }
    }
    __syncthreads();
    {   // P[v][o] = bias[o] + emb[v,:]·Wx[o,:]; thread: o = tid&255, 2 v-groups
        const float* embT = (const float*)(smem + SM_EMBT);
        const int o = tid & 255;
        const int vg0 = (tid >> 8) * 2;
        const float bo = bias[o];
        const float4* wrow = (const float4*)(W + (size_t)o * (2 * Hdim));
        for (int vg = vg0; vg < vg0 + 2; ++vg) {
            unsigned long long acc[8];
#pragma unroll
            for (int i = 0; i < 8; ++i) acc[i] = pack2(0.f, 0.f);
            for (int k4 = 0; k4 < Hdim / 4; ++k4) {
                float4 wv = wrow[k4];
#pragma unroll
                for (int kk = 0; kk < 4; ++kk) {
                    int k = k4 * 4 + kk;
                    float w = (kk == 0) ? wv.x : (kk == 1) ? wv.y : (kk == 2) ? wv.z : wv.w;
                    unsigned long long wpair = pack2(w, w);
                    const ulonglong2* ep =
                        (const ulonglong2*)(embT + (size_t)k * ESTR + vg * 16);
                    ulonglong2 e0 = ep[0], e1 = ep[1], e2 = ep[2], e3 = ep[3];
                    ffma2(acc[0], wpair, e0.x); ffma2(acc[1], wpair, e0.y);
                    ffma2(acc[2], wpair, e1.x); ffma2(acc[3], wpair, e1.y);
                    ffma2(acc[4], wpair, e2.x); ffma2(acc[5], wpair, e2.y);
                    ffma2(acc[6], wpair, e3.x); ffma2(acc[7], wpair, e3.y);
                }
            }
#pragma unroll
            for (int i = 0; i < 8; ++i) {
                float lo = __uint_as_float((uint32_t)(acc[i] & 0xffffffffu));
                float hi = __uint_as_float((uint32_t)(acc[i] >> 32));
                int v0 = vg * 16 + 2 * i;
                Psm[(size_t)v0 * PSTR + o]       = bo + lo;
                Psm[(size_t)(v0 + 1) * PSTR + o] = bo + hi;
            }
        }
    }
    // B fragments: warp owns outputs [16w, 16w+16) -> 2 n8 tiles
    uint32_t breg[2][16][2];
#pragma unroll
    for (int nt = 0; nt < 2; ++nt) {
        int n = wid * 16 + nt * 8 + g;
        const float* wr = W + (size_t)n * (2 * Hdim) + Hdim;
#pragma unroll
        for (int c = 0; c < 16; ++c) {
            float2 lo = *(const float2*)&wr[2 * r + 16 * c];
            float2 hi = *(const float2*)&wr[2 * r + 8 + 16 * c];
            __half2 hlo = __floats2half2_rn(lo.x, lo.y);
            __half2 hhi = __floats2half2_rn(hi.x, hi.y);
            breg[nt][c][0] = *(uint32_t*)&hlo;
            breg[nt][c][1] = *(uint32_t*)&hhi;
        }
    }
    for (int idx = tid; idx < NB * Tdim; idx += NTH) {
        int b = idx >> 9, t = idx & 511;
        toks[t * NB + b] = tokens[(size_t)(bbase + b) * Tdim + t];
    }
    // h(0) in fragment layout: thread (wid=c, g, r) packs its own slot entry.
    {
        int c = wid;
        int k0 = 16 * c + 2 * r;
        const float* h0b = h0 + (size_t)bbase * Hdim;
        __half2 q0 = __floats2half2_rn(h0b[(size_t)g * Hdim + k0],
                                       h0b[(size_t)g * Hdim + k0 + 1]);
        __half2 q1 = __floats2half2_rn(h0b[(size_t)(g + 8) * Hdim + k0],
                                       h0b[(size_t)(g + 8) * Hdim + k0 + 1]);
        __half2 q2 = __floats2half2_rn(h0b[(size_t)g * Hdim + k0 + 8],
                                       h0b[(size_t)g * Hdim + k0 + 9]);
        __half2 q3 = __floats2half2_rn(h0b[(size_t)(g + 8) * Hdim + k0 + 8],
                                       h0b[(size_t)(g + 8) * Hdim + k0 + 9]);
        sts128(sbase + SM_F0 + (uint32_t)(c * 512 + lane * 16),
               *(uint32_t*)&q0, *(uint32_t*)&q1, *(uint32_t*)&q2, *(uint32_t*)&q3);
    }
    if (tid == 0) MBAR_INIT(mbar, NTH);
    __syncthreads();
    MBAR_ARRIVE(mbar);       // phase 0: h(0) published

    const int o0 = wid * 16 + 2 * r;
    const uint32_t fr_lane = (uint32_t)(lane * 16);
    const uint32_t slot_own = (uint32_t)(wid * 512) + fr_lane;
    float* const outcta = out + (size_t)bbase * Hdim;

    // ============== Recurrent loop ==============
    for (int t = 0; t < Tdim; ++t) {
        // P/token prefetch (stable regions; independent of the wait)
        const int tk0 = toks[t * NB + g];
        const int tk1 = toks[t * NB + g + 8];
        float dA[2][4], dB[2][4];
#pragma unroll
        for (int nt = 0; nt < 2; ++nt) {
            float2 p0 = *(const float2*)&Psm[(size_t)tk0 * PSTR + o0 + nt * 8];
            float2 p1 = *(const float2*)&Psm[(size_t)tk1 * PSTR + o0 + nt * 8];
            dA[nt][0] = p0.x; dA[nt][1] = p0.y;
            dA[nt][2] = p1.x; dA[nt][3] = p1.y;
            dB[nt][0] = 0.f;  dB[nt][1] = 0.f;
            dB[nt][2] = 0.f;  dB[nt][3] = 0.f;
        }

        mbar_wait(mbar, (uint32_t)(t & 1));
        const uint32_t abuf = sbase + ((t & 1) ? SM_F1 : SM_F0) + fr_lane;

        // two independent 8-deep chains per n-tile, interleaved for ILP;
        // A-fragments come straight from the fragment slots (LDS.128).
#pragma unroll
        for (int cc = 0; cc < 8; ++cc) {
            uint32_t a0[4], a1[4];
            lds128(a0, abuf + (uint32_t)cc * 512);
            lds128(a1, abuf + (uint32_t)(cc + 8) * 512);
            mma16816(dA[0], a0, breg[0][cc][0], breg[0][cc][1]);
            mma16816(dB[0], a1, breg[0][cc + 8][0], breg[0][cc + 8][1]);
            mma16816(dA[1], a0, breg[1][cc][0], breg[1][cc][1]);
            mma16816(dB[1], a1, breg[1][cc + 8][0], breg[1][cc + 8][1]);
        }

        // fold chains, sigmoid, publish h(t+1) fragment (ONE STS.128), arrive
        float s[2][4];
#pragma unroll
        for (int nt = 0; nt < 2; ++nt) {
            s[nt][0] = sigmoid_t(dA[nt][0] + dB[nt][0]);
            s[nt][1] = sigmoid_t(dA[nt][1] + dB[nt][1]);
            s[nt][2] = sigmoid_t(dA[nt][2] + dB[nt][2]);
            s[nt][3] = sigmoid_t(dA[nt][3] + dB[nt][3]);
        }
        {
            __half2 q0 = __floats2half2_rn(s[0][0], s[0][1]);
            __half2 q1 = __floats2half2_rn(s[0][2], s[0][3]);
            __half2 q2 = __floats2half2_rn(s[1][0], s[1][1]);
            __half2 q3 = __floats2half2_rn(s[1][2], s[1][3]);
            const uint32_t fnext = sbase + ((t & 1) ? SM_F0 : SM_F1) + slot_own;
            sts128(fnext, *(uint32_t*)&q0, *(uint32_t*)&q1,
                   *(uint32_t*)&q2, *(uint32_t*)&q3);
        }
        MBAR_ARRIVE(mbar);

        // output drain in the post-arrive shadow (exact f32 values)
        float* outp = outcta + (size_t)t * (Bdim * Hdim);
#pragma unroll
        for (int nt = 0; nt < 2; ++nt) {
            int o = o0 + nt * 8;
            *(float2*)&outp[(size_t)g * Hdim + o]       = make_float2(s[nt][0], s[nt][1]);
            *(float2*)&outp[(size_t)(g + 8) * Hdim + o] = make_float2(s[nt][2], s[nt][3]);
        }
    }
}

// ---------------------------------------------------------------------------
// Harness entry.
// Inputs: tokens(i32 2048x512), h0(f32 2048x256), emb(f32 64x256),
//         W(f32 256x512), b(f32 256).  Output: f32 (512,2048,256)
// ---------------------------------------------------------------------------
extern "C" void kernel_launch(void* const* d_in, const int* in_sizes, int n_in,
                              void* d_out, int out_size) {
    const int*   tokens = (const int*)d_in[0];
    const float* h0     = (const float*)d_in[1];
    const float* emb    = (const float*)d_in[2];
    const float* W      = (const float*)d_in[3];
    const float* bias   = (const float*)d_in[4];
    float*       out    = (float*)d_out;
    (void)in_sizes; (void)n_in; (void)out_size;

    cudaFuncSetAttribute(k_rnn, cudaFuncAttributeMaxDynamicSharedMemorySize, SMEM_TOTAL);
    k_rnn<<<Bdim / NB, NTH, SMEM_TOTAL>>>(tokens, h0, emb, W, bias, out);
}